// round 3
// baseline (speedup 1.0000x reference)
#include <cuda_runtime.h>
#include <cstdint>

// DCNv2 forward, fp32.
// Shapes: input (8,256,64,64), w_om (27,256,3,3), b_om (27),
//         w_dcn (256,256,3,3), b_dcn (256), out (8,256,64,64).

typedef unsigned long long ull;

#define BB   8
#define CIN  256
#define COUT 256
#define HW   64
#define KKN  9

// Scratch (static device arrays: allocation-free).
// g_om layout: [grp(0=dy,1=dx,2=mask)][b][k][y][x]
__device__ float g_om[3 * BB * KKN * HW * HW];
// g_wT layout: [c*9+k][oc]
__device__ float g_wT[CIN * KKN * COUT];

__device__ __forceinline__ ull fma2(ull a, ull b, ull c) {
    ull d;
    asm("fma.rn.f32x2 %0, %1, %2, %3;" : "=l"(d) : "l"(a), "l"(b), "l"(c));
    return d;
}

// ---------------------------------------------------------------------------
// Kernel W: transpose w_dcn (oc, c*9) -> g_wT (c*9, oc)
// ---------------------------------------------------------------------------
__global__ void transpose_w_kernel(const float* __restrict__ w_dcn) {
    int i = blockIdx.x * 256 + threadIdx.x;
    if (i < CIN * KKN * COUT) {
        int ck = i >> 8;      // 0..2303
        int oc = i & 255;
        g_wT[i] = w_dcn[oc * (CIN * KKN) + ck];
    }
}

// ---------------------------------------------------------------------------
// Kernel A: offset/mask conv (27 out-channels, 3x3, pad 1) + bias + sigmoid
// Block: one (b, y) row. 256 threads; threads compute (oc, 8-px group).
// ---------------------------------------------------------------------------
__global__ __launch_bounds__(256) void om_kernel(
    const float* __restrict__ input,
    const float* __restrict__ w_om,
    const float* __restrict__ b_om) {
    __shared__ float s_in[3 * 68];   // 3 rows x (x=-1..64), padded
    __shared__ float s_w[243];       // 27 oc x 9 taps for current c

    const int y   = blockIdx.x;
    const int b   = blockIdx.y;
    const int tid = threadIdx.x;
    const int oc  = tid >> 3;        // 0..31 (active < 27)
    const int xg  = tid & 7;
    const int x0  = xg << 3;         // 8 consecutive x per thread

    float acc[8];
#pragma unroll
    for (int i = 0; i < 8; ++i) acc[i] = 0.f;

    for (int c = 0; c < CIN; ++c) {
        __syncthreads();
        if (tid < 198) {
            int r  = tid / 66;
            int xi = tid - r * 66;        // 0..65
            int xx = xi - 1;              // -1..64
            int yy = y - 1 + r;
            float v = 0.f;
            if (yy >= 0 && yy < HW && xx >= 0 && xx < HW)
                v = input[(((size_t)b * CIN + c) * HW + yy) * HW + xx];
            s_in[r * 68 + xi] = v;
        }
        if (tid < 243) {
            int o = tid / 9, k = tid - o * 9;
            s_w[tid] = w_om[(o * CIN + c) * KKN + k];
        }
        __syncthreads();
        if (oc < 27) {
#pragma unroll
            for (int r = 0; r < 3; ++r) {
                const float w0 = s_w[oc * 9 + r * 3 + 0];
                const float w1 = s_w[oc * 9 + r * 3 + 1];
                const float w2 = s_w[oc * 9 + r * 3 + 2];
                const float* row = s_in + r * 68 + x0;  // row[i] -> input x = x0+i-1
                float v0 = row[0], v1 = row[1];
#pragma unroll
                for (int xi = 0; xi < 8; ++xi) {
                    float v2 = row[xi + 2];
                    acc[xi] += w0 * v0 + w1 * v1 + w2 * v2;
                    v0 = v1; v1 = v2;
                }
            }
        }
    }

    if (oc < 27) {
        const float bias = b_om[oc];
        const int grp = oc / 9;
        const int k   = oc - grp * 9;
        float* dst = g_om + (((size_t)grp * BB + b) * KKN + k) * (HW * HW) + y * HW + x0;
#pragma unroll
        for (int xi = 0; xi < 8; ++xi) {
            float v = acc[xi] + bias;
            if (grp == 2) v = 1.f / (1.f + expf(-v));
            dst[xi] = v;
        }
    }
}

// ---------------------------------------------------------------------------
// Kernel B: fused bilinear sampling + implicit GEMM.
// Block: (y row, 128-oc tile, b). 256 threads.
// Thread (tx=tid&15, ty=tid>>4) owns 8 oc x 4 px, accumulated as f32x2 pairs.
// Smem: meta (bilinear w/idx per k,px), cols tile (4c x 9k x 64px),
//       weight tile duplicated into f32 pairs for FFMA2.
// ---------------------------------------------------------------------------
#define SMEM_BYTES (9216 + 9216 + 9216 + 36864)   // 64512

__global__ __launch_bounds__(256, 2) void dcn_main_kernel(
    const float* __restrict__ input,
    const float* __restrict__ b_dcn,
    float* __restrict__ out) {
    extern __shared__ char smem[];
    float* s_w    = (float*)smem;            // [4][576]  bilinear weights (mask folded)
    int*   s_idx  = (int*)(smem + 9216);     // [4][576]  clamped gather indices
    float* s_cols = (float*)(smem + 18432);  // [36][64]  sampled cols (cc*9+k, px)
    ull*   s_wd   = (ull*)(smem + 27648);    // [36][128] duplicated weight pairs

    const int y   = blockIdx.x;
    const int ocb = blockIdx.y << 7;
    const int b   = blockIdx.z;
    const int tid = threadIdx.x;
    const int tx  = tid & 15;
    const int ty  = tid >> 4;

    // Phase 1: per-(k,px) bilinear metadata
    for (int j = tid; j < 576; j += 256) {
        const int k  = j >> 6;
        const int px = j & 63;
        const float* p = g_om + (((size_t)b * KKN + k) * HW + y) * HW + px;
        const float dy = p[0];
        const float dx = p[(size_t)BB * KKN * HW * HW];
        const float m  = p[(size_t)2 * BB * KKN * HW * HW];
        const int ki = k / 3, kj = k - ki * 3;
        const float py  = (float)(y - 1 + ki) + dy;
        const float pxx = (float)(px - 1 + kj) + dx;
        const float y0f = floorf(py), x0f = floorf(pxx);
        const float ly = py - y0f, lx = pxx - x0f;
        const int y0 = (int)y0f, x0 = (int)x0f;
        const int y1 = y0 + 1,  x1 = x0 + 1;
        const bool vy0 = (y0 >= 0) && (y0 < HW);
        const bool vy1 = (y1 >= 0) && (y1 < HW);
        const bool vx0 = (x0 >= 0) && (x0 < HW);
        const bool vx1 = (x1 >= 0) && (x1 < HW);
        const int cy0 = min(max(y0, 0), HW - 1), cy1 = min(max(y1, 0), HW - 1);
        const int cx0 = min(max(x0, 0), HW - 1), cx1 = min(max(x1, 0), HW - 1);
        s_w[j]          = (vy0 && vx0) ? (1.f - ly) * (1.f - lx) * m : 0.f;
        s_w[576 + j]    = (vy0 && vx1) ? (1.f - ly) * lx * m : 0.f;
        s_w[1152 + j]   = (vy1 && vx0) ? ly * (1.f - lx) * m : 0.f;
        s_w[1728 + j]   = (vy1 && vx1) ? ly * lx * m : 0.f;
        s_idx[j]        = cy0 * HW + cx0;
        s_idx[576 + j]  = cy0 * HW + cx1;
        s_idx[1152 + j] = cy1 * HW + cx0;
        s_idx[1728 + j] = cy1 * HW + cx1;
    }

    ull accA[8], accB[8];
#pragma unroll
    for (int o = 0; o < 8; ++o) { accA[o] = 0ull; accB[o] = 0ull; }

    __syncthreads();

    const float* ipb = input + (size_t)b * CIN * HW * HW;
    for (int c0 = 0; c0 < CIN; c0 += 4) {
        // Fill cols tile: 4 channels x 9 taps x 64 px = 2304 samples
        const float* ip = ipb + (size_t)c0 * HW * HW;
#pragma unroll
        for (int it = 0; it < 9; ++it) {
            const int j  = tid + it * 256;     // 0..2303
            const int cc = j / 576;
            const int r  = j - cc * 576;       // k*64+px
            const float* pl = ip + (cc << 12);
            float v = s_w[r]        * __ldg(pl + s_idx[r])
                    + s_w[576 + r]  * __ldg(pl + s_idx[576 + r])
                    + s_w[1152 + r] * __ldg(pl + s_idx[1152 + r])
                    + s_w[1728 + r] * __ldg(pl + s_idx[1728 + r]);
            s_cols[j] = v;
        }
        // Fill weight tile: [cc*9+k][oc 0..127], duplicated into float2 pairs.
        // 36 rows x 128 oc = 4608 entries -> 18 iterations of 256 threads.
        const float* wp = g_wT + (size_t)c0 * KKN * COUT + ocb;
#pragma unroll
        for (int it = 0; it < 18; ++it) {
            const int j  = tid + it * 256;     // 0..4607
            const int ck = j >> 7;             // 0..35
            const int oc = j & 127;
            const float w = wp[ck * COUT + oc];
            float2 d2 = make_float2(w, w);
            s_wd[j] = *(ull*)&d2;
        }
        __syncthreads();

#pragma unroll
        for (int q = 0; q < 36; ++q) {
            const ull* cvp = (const ull*)(s_cols + (q << 6)) + (tx << 1);
            const ull cv0 = cvp[0];
            const ull cv1 = cvp[1];
            const ull* wvp = s_wd + (q << 7) + (ty << 3);
#pragma unroll
            for (int o = 0; o < 8; ++o) {
                const ull wv = wvp[o];
                accA[o] = fma2(wv, cv0, accA[o]);
                accB[o] = fma2(wv, cv1, accB[o]);
            }
        }
        __syncthreads();
    }

    // Epilogue: add bias, store float4 per oc
    const int px4 = tx << 2;
#pragma unroll
    for (int o = 0; o < 8; ++o) {
        const int oc = ocb + (ty << 3) + o;
        const float bias = b_dcn[oc];
        float ax, ay, bx, by;
        asm("mov.b64 {%0,%1}, %2;" : "=f"(ax), "=f"(ay) : "l"(accA[o]));
        asm("mov.b64 {%0,%1}, %2;" : "=f"(bx), "=f"(by) : "l"(accB[o]));
        float4 r4 = make_float4(ax + bias, ay + bias, bx + bias, by + bias);
        *(float4*)(out + (((size_t)b * COUT + oc) * HW + y) * HW + px4) = r4;
    }
}

// ---------------------------------------------------------------------------
extern "C" void kernel_launch(void* const* d_in, const int* in_sizes, int n_in,
                              void* d_out, int out_size) {
    const float* input = (const float*)d_in[0];
    const float* w_om  = (const float*)d_in[1];
    const float* b_om  = (const float*)d_in[2];
    const float* w_dcn = (const float*)d_in[3];
    const float* b_dcn = (const float*)d_in[4];
    float* out = (float*)d_out;

    // Idempotent, executes eagerly (not a stream op) — safe under graph capture.
    cudaFuncSetAttribute(dcn_main_kernel,
                         cudaFuncAttributeMaxDynamicSharedMemorySize, SMEM_BYTES);

    transpose_w_kernel<<<(CIN * KKN * COUT + 255) / 256, 256>>>(w_dcn);
    om_kernel<<<dim3(HW, BB), 256>>>(input, w_om, b_om);
    dcn_main_kernel<<<dim3(HW, 2, BB), 256, SMEM_BYTES>>>(input, b_dcn, out);
}

// round 7
// speedup vs baseline: 1.5994x; 1.5994x over previous
#include <cuda_runtime.h>
#include <cuda_bf16.h>
#include <cstdint>

// DCNv2 forward. Offset conv on fp32 CUDA cores; main 38.7-GFLOP einsum on
// tensor cores via mma.sync.m16n8k16 bf16 with hi/lo split (Ootomo 3-term,
// error ~2^-16 per product). compute_100-safe: no tcgen05/TMEM/wgmma.
// Shapes: input (8,256,64,64), w_om (27,256,3,3), b_om (27),
//         w_dcn (256,256,3,3), b_dcn (256), out (8,256,64,64).

typedef unsigned int uint;
typedef unsigned short ushort;

#define BB     8
#define CIN    256
#define COUT   256
#define HW     64
#define KKN    9
#define KTOT   2304          // dense K = 256 ch x 9 taps
#define CHUNKS 72            // K chunks of 32 (2 k16 steps each)

// ---------------- device scratch (static: allocation-free) ----------------
// g_om layout: [grp(0=dy,1=dx,2=mask)][b][k][y][x]
__device__ float g_om[3 * BB * KKN * HW * HW];
// dense pre-split weights, chunk-major: [chunk][oc][32] bf16
__device__ __align__(16) __nv_bfloat16 g_wbh[CHUNKS * COUT * 32];
__device__ __align__(16) __nv_bfloat16 g_wbl[CHUNKS * COUT * 32];

__device__ __forceinline__ uint smem_u32(const void* p) {
    uint a;
    asm("{ .reg .u64 t; cvta.to.shared.u64 t, %1; cvt.u32.u64 %0, t; }"
        : "=r"(a) : "l"(p));
    return a;
}

#define LDM_X4(r, addr) \
    asm volatile("ldmatrix.sync.aligned.m8n8.x4.shared.b16 {%0,%1,%2,%3}, [%4];" \
        : "=r"((r)[0]), "=r"((r)[1]), "=r"((r)[2]), "=r"((r)[3]) : "r"(addr))

#define MMA16816(d, a, b) \
    asm volatile("mma.sync.aligned.m16n8k16.row.col.f32.bf16.bf16.f32 " \
        "{%0,%1,%2,%3},{%4,%5,%6,%7},{%8,%9},{%0,%1,%2,%3};" \
        : "+f"((d)[0]), "+f"((d)[1]), "+f"((d)[2]), "+f"((d)[3]) \
        : "r"((a)[0]), "r"((a)[1]), "r"((a)[2]), "r"((a)[3]), \
          "r"((b)[0]), "r"((b)[1]))

// ---------------------------------------------------------------------------
// Kernel P: dense bf16-split weights, chunk-major [t][oc][32], kk = t*32+kkl,
// c = kk/9, k = kk%9.
// ---------------------------------------------------------------------------
__global__ void prep_w_kernel(const float* __restrict__ w_dcn) {
    int i = blockIdx.x * 256 + threadIdx.x;   // < 72*256*32 = 589824
    int kkl = i & 31;
    int oc  = (i >> 5) & 255;
    int t   = i >> 13;
    int kk  = t * 32 + kkl;
    int c   = kk / 9;
    int k   = kk - c * 9;
    float w = w_dcn[(oc * CIN + c) * KKN + k];
    __nv_bfloat16 h = __float2bfloat16(w);
    g_wbh[i] = h;
    g_wbl[i] = __float2bfloat16(w - __bfloat162float(h));
}

// ---------------------------------------------------------------------------
// Kernel A: offset/mask conv (27 oc, 3x3, pad 1) + bias + sigmoid.
// ---------------------------------------------------------------------------
__global__ __launch_bounds__(256) void om_kernel(
    const float* __restrict__ input,
    const float* __restrict__ w_om,
    const float* __restrict__ b_om) {
    __shared__ float s_in[4][3 * 68];
    __shared__ float s_w[4][244];

    const int y   = blockIdx.x;
    const int b   = blockIdx.y;
    const int tid = threadIdx.x;
    const int oc  = tid >> 3;
    const int x0  = (tid & 7) << 3;

    float acc[8];
#pragma unroll
    for (int i = 0; i < 8; ++i) acc[i] = 0.f;

    for (int c0 = 0; c0 < CIN; c0 += 4) {
        __syncthreads();
        if (tid < 198) {
            int r  = tid / 66;
            int xi = tid - r * 66;
            int xx = xi - 1, yy = y - 1 + r;
            bool ok = (yy >= 0 && yy < HW && xx >= 0 && xx < HW);
            int yyc = min(max(yy, 0), HW - 1), xxc = min(max(xx, 0), HW - 1);
            const float* base = input + (((size_t)b * CIN + c0) * HW + yyc) * HW + xxc;
#pragma unroll
            for (int cc = 0; cc < 4; ++cc)
                s_in[cc][r * 68 + xi] = ok ? base[cc * HW * HW] : 0.f;
        }
        for (int j = tid; j < 972; j += 256) {
            int cc = j / 243, t = j - cc * 243;
            int o = t / 9, k = t - o * 9;
            s_w[cc][t] = w_om[(o * CIN + c0 + cc) * KKN + k];
        }
        __syncthreads();
        if (oc < 27) {
#pragma unroll
            for (int cc = 0; cc < 4; ++cc) {
#pragma unroll
                for (int r = 0; r < 3; ++r) {
                    float w0 = s_w[cc][oc * 9 + r * 3 + 0];
                    float w1 = s_w[cc][oc * 9 + r * 3 + 1];
                    float w2 = s_w[cc][oc * 9 + r * 3 + 2];
                    const float* row = s_in[cc] + r * 68 + x0;
                    float v0 = row[0], v1 = row[1];
#pragma unroll
                    for (int xi = 0; xi < 8; ++xi) {
                        float v2 = row[xi + 2];
                        acc[xi] += w0 * v0 + w1 * v1 + w2 * v2;
                        v0 = v1; v1 = v2;
                    }
                }
            }
        }
    }

    if (oc < 27) {
        const float bias = b_om[oc];
        const int grp = oc / 9;
        const int k   = oc - grp * 9;
        float* dst = g_om + (((size_t)grp * BB + b) * KKN + k) * (HW * HW) + y * HW + x0;
#pragma unroll
        for (int xi = 0; xi < 8; ++xi) {
            float v = acc[xi] + bias;
            if (grp == 2) v = 1.f / (1.f + expf(-v));
            dst[xi] = v;
        }
    }
}

// ---------------------------------------------------------------------------
// Kernel B: fused bilinear sampling + mma.sync GEMM.
// CTA = (2 image rows = 128 px, batch). M=128, N=256, K dense 2304.
// Warp tile 64x64; 8 warps (2 M x 4 N). Double-buffered smem, sync pipeline.
// Smem rows padded to 80 B -> conflict-free ldmatrix (5r mod 8 permutation).
// ---------------------------------------------------------------------------
#define ABYTES 10240            // 128 rows * 80 B (one split)
#define BBYTES 20480            // 256 rows * 80 B (one split)
#define STGB   61440            // Ah | Al | Bh | Bl
#define SM_WM  0                // float4[1152]
#define SM_IM  18432            // ushort4[1152]
#define SM_BUF 27648
#define SM_TOTAL (SM_BUF + 2 * STGB)   // 150528

__device__ __forceinline__ void stage_chunk(
    char* smem, int bufoff, int t, int b, int tid,
    const float4* s_wm4, const ushort4* s_im4,
    const float* __restrict__ input) {
    // ---- B: one oc row per thread, 64 B per split ----
    {
        const uint4* sh = (const uint4*)(g_wbh + ((size_t)t * COUT + tid) * 32);
        const uint4* sl = (const uint4*)(g_wbl + ((size_t)t * COUT + tid) * 32);
        char* Bh = smem + bufoff + 2 * ABYTES + tid * 80;
        char* Bl = Bh + BBYTES;
#pragma unroll
        for (int q = 0; q < 4; ++q) {
            *(uint4*)(Bh + q * 16) = sh[q];
            *(uint4*)(Bl + q * 16) = sl[q];
        }
    }
    // ---- A: thread covers (px = tid>>1, 16 kk starting at (tid&1)*16) ----
    const int px  = tid >> 1;
    const int kh  = (tid & 1) * 16;
    const int kks = t * 32 + kh;
    int c = kks / 9;
    int k = kks - c * 9;
    const float* pl = input + (((size_t)b * CIN + c) << 12);
    const int mbase = (px >> 6) * 576 + (px & 63);
    uint hi[8], lo[8];
#pragma unroll
    for (int i = 0; i < 16; ++i) {
        int m = mbase + k * 64;
        float4  w4 = s_wm4[m];
        ushort4 i4 = s_im4[m];
        float v = w4.x * __ldg(pl + i4.x) + w4.y * __ldg(pl + i4.y)
                + w4.z * __ldg(pl + i4.z) + w4.w * __ldg(pl + i4.w);
        __nv_bfloat16 h = __float2bfloat16(v);
        __nv_bfloat16 l = __float2bfloat16(v - __bfloat162float(h));
        uint hu = (uint)__bfloat16_as_ushort(h);
        uint lu = (uint)__bfloat16_as_ushort(l);
        if (i & 1) { hi[i >> 1] |= hu << 16; lo[i >> 1] |= lu << 16; }
        else       { hi[i >> 1]  = hu;       lo[i >> 1]  = lu; }
        if (++k == 9) { k = 0; pl += HW * HW; }
    }
    char* Ah = smem + bufoff + px * 80 + kh * 2;
    char* Al = Ah + ABYTES;
    *(uint4*)(Ah)      = make_uint4(hi[0], hi[1], hi[2], hi[3]);
    *(uint4*)(Ah + 16) = make_uint4(hi[4], hi[5], hi[6], hi[7]);
    *(uint4*)(Al)      = make_uint4(lo[0], lo[1], lo[2], lo[3]);
    *(uint4*)(Al + 16) = make_uint4(lo[4], lo[5], lo[6], lo[7]);
}

__global__ __launch_bounds__(256, 1) void dcn_main_mma(
    const float* __restrict__ input,
    const float* __restrict__ b_dcn,
    float* __restrict__ out) {
    extern __shared__ char smem[];
    const int tid  = threadIdx.x;
    const int wid  = tid >> 5;
    const int lane = tid & 31;
    const int b    = blockIdx.y;
    const int y0   = blockIdx.x * 2;

    const uint sbase = smem_u32(smem);
    float4*  s_wm4 = (float4*)(smem + SM_WM);
    ushort4* s_im4 = (ushort4*)(smem + SM_IM);

    // Phase 1: bilinear metadata for 2 rows x 9 taps x 64 px (mask folded).
    for (int j = tid; j < 1152; j += 256) {
        int rs  = j / 576;
        int rem = j - rs * 576;
        int k   = rem >> 6;
        int px  = rem & 63;
        int y   = y0 + rs;
        const float* p = g_om + (((size_t)b * KKN + k) * HW + y) * HW + px;
        float dy = p[0];
        float dx = p[(size_t)BB * KKN * HW * HW];
        float m  = p[(size_t)2 * BB * KKN * HW * HW];
        int ki = k / 3, kj = k - ki * 3;
        float py  = (float)(y - 1 + ki) + dy;
        float pxx = (float)(px - 1 + kj) + dx;
        float y0f = floorf(py), x0f = floorf(pxx);
        float ly = py - y0f, lx = pxx - x0f;
        int yy0 = (int)y0f, xx0 = (int)x0f;
        int yy1 = yy0 + 1,  xx1 = xx0 + 1;
        bool vy0 = (yy0 >= 0) && (yy0 < HW);
        bool vy1 = (yy1 >= 0) && (yy1 < HW);
        bool vx0 = (xx0 >= 0) && (xx0 < HW);
        bool vx1 = (xx1 >= 0) && (xx1 < HW);
        int cy0 = min(max(yy0, 0), HW - 1), cy1 = min(max(yy1, 0), HW - 1);
        int cx0 = min(max(xx0, 0), HW - 1), cx1 = min(max(xx1, 0), HW - 1);
        float w00 = (vy0 && vx0) ? (1.f - ly) * (1.f - lx) * m : 0.f;
        float w01 = (vy0 && vx1) ? (1.f - ly) * lx * m : 0.f;
        float w10 = (vy1 && vx0) ? ly * (1.f - lx) * m : 0.f;
        float w11 = (vy1 && vx1) ? ly * lx * m : 0.f;
        s_wm4[j] = make_float4(w00, w01, w10, w11);
        s_im4[j] = make_ushort4((ushort)(cy0 * HW + cx0), (ushort)(cy0 * HW + cx1),
                                (ushort)(cy1 * HW + cx0), (ushort)(cy1 * HW + cx1));
    }
    __syncthreads();

    // Warp tiling: 2 warps along M (64), 4 along N (64).
    const int mwarp = (wid & 1) * 64;
    const int nwarp = (wid >> 1) * 64;
    // ldmatrix lane address components.
    const uint aLane = (uint)((mwarp + (lane & 15)) * 80 + ((lane >> 4) & 1) * 16);
    const uint bLane = (uint)((nwarp + (lane & 7) + ((lane >> 4) & 1) * 8) * 80
                              + ((lane >> 3) & 1) * 16);

    float acc[4][8][4];
#pragma unroll
    for (int mt = 0; mt < 4; ++mt)
#pragma unroll
        for (int nt = 0; nt < 8; ++nt)
#pragma unroll
            for (int q = 0; q < 4; ++q) acc[mt][nt][q] = 0.f;

    stage_chunk(smem, SM_BUF, 0, b, tid, s_wm4, s_im4, input);
    __syncthreads();

#pragma unroll 1
    for (int t = 0; t < CHUNKS; ++t) {
        const int s = t & 1;
        if (t + 1 < CHUNKS)
            stage_chunk(smem, SM_BUF + (s ^ 1) * STGB, t + 1, b, tid, s_wm4, s_im4, input);

        const uint aBase = sbase + SM_BUF + s * STGB + aLane;
        const uint bBase = sbase + SM_BUF + s * STGB + 2 * ABYTES + bLane;
#pragma unroll
        for (int ks = 0; ks < 2; ++ks) {
            uint ah[4][4], al[4][4];
#pragma unroll
            for (int mt = 0; mt < 4; ++mt) {
                uint aa = aBase + mt * (16 * 80) + ks * 32;
                LDM_X4(ah[mt], aa);
                LDM_X4(al[mt], aa + ABYTES);
            }
#pragma unroll
            for (int g = 0; g < 4; ++g) {
                uint bh[4], bl[4];
                uint ba = bBase + g * (16 * 80) + ks * 32;
                LDM_X4(bh, ba);
                LDM_X4(bl, ba + BBYTES);
#pragma unroll
                for (int mt = 0; mt < 4; ++mt) {
                    MMA16816(acc[mt][2 * g],     ah[mt], bh);
                    MMA16816(acc[mt][2 * g],     ah[mt], bl);
                    MMA16816(acc[mt][2 * g],     al[mt], bh);
                    MMA16816(acc[mt][2 * g + 1], ah[mt], bh + 2);
                    MMA16816(acc[mt][2 * g + 1], ah[mt], bl + 2);
                    MMA16816(acc[mt][2 * g + 1], al[mt], bh + 2);
                }
            }
        }
        __syncthreads();
    }

    // Epilogue: register accumulators -> gmem, bias added.
    const int tq = lane >> 2, tr = lane & 3;
    float bz[8][2];
#pragma unroll
    for (int nt = 0; nt < 8; ++nt) {
        int oc = nwarp + nt * 8 + tr * 2;
        bz[nt][0] = __ldg(b_dcn + oc);
        bz[nt][1] = __ldg(b_dcn + oc + 1);
    }
    const int ybase = y0 + (mwarp >> 6);
#pragma unroll
    for (int mt = 0; mt < 4; ++mt) {
        int x = mt * 16 + tq;
#pragma unroll
        for (int nt = 0; nt < 8; ++nt) {
            int oc = nwarp + nt * 8 + tr * 2;
            float* orow = out + ((size_t)(b * COUT + oc)) * (HW * HW) + ybase * HW + x;
            orow[0]        = acc[mt][nt][0] + bz[nt][0];
            orow[HW * HW]  = acc[mt][nt][1] + bz[nt][1];
            orow[8]        = acc[mt][nt][2] + bz[nt][0];
            orow[HW * HW + 8] = acc[mt][nt][3] + bz[nt][1];
        }
    }
}

// ---------------------------------------------------------------------------
extern "C" void kernel_launch(void* const* d_in, const int* in_sizes, int n_in,
                              void* d_out, int out_size) {
    const float* input = (const float*)d_in[0];
    const float* w_om  = (const float*)d_in[1];
    const float* b_om  = (const float*)d_in[2];
    const float* w_dcn = (const float*)d_in[3];
    const float* b_dcn = (const float*)d_in[4];
    float* out = (float*)d_out;

    cudaFuncSetAttribute(dcn_main_mma,
                         cudaFuncAttributeMaxDynamicSharedMemorySize, SM_TOTAL);

    prep_w_kernel<<<(CHUNKS * COUT * 32) / 256, 256>>>(w_dcn);
    om_kernel<<<dim3(HW, BB), 256>>>(input, w_om, b_om);
    dcn_main_mma<<<dim3(HW / 2, BB), 256, SM_TOTAL>>>(input, b_dcn, out);
}

// round 9
// speedup vs baseline: 1.8274x; 1.1425x over previous
#include <cuda_runtime.h>
#include <cuda_bf16.h>
#include <cstdint>

// DCNv2 forward. Offset conv on fp32 CUDA cores; main 38.7-GFLOP einsum on
// tensor cores via mma.sync.m16n8k16 bf16 with hi/lo split (Ootomo 3-term).
// R8: main kernel 512 threads (16 warps, warp tile 32x64), px-major coalesced
// gather mapping. Launch order om->prep->main so ncu captures om.

typedef unsigned int uint;
typedef unsigned short ushort;

#define BB     8
#define CIN    256
#define COUT   256
#define HW     64
#define KKN    9
#define KTOT   2304
#define CHUNKS 72            // K chunks of 32 (2 k16 steps each)

// ---------------- device scratch (static: allocation-free) ----------------
__device__ float g_om[3 * BB * KKN * HW * HW];
// dense pre-split weights, chunk-major: [chunk][oc][32] bf16
__device__ __align__(16) __nv_bfloat16 g_wbh[CHUNKS * COUT * 32];
__device__ __align__(16) __nv_bfloat16 g_wbl[CHUNKS * COUT * 32];

__device__ __forceinline__ uint smem_u32(const void* p) {
    uint a;
    asm("{ .reg .u64 t; cvta.to.shared.u64 t, %1; cvt.u32.u64 %0, t; }"
        : "=r"(a) : "l"(p));
    return a;
}

#define LDM_X4(r, addr) \
    asm volatile("ldmatrix.sync.aligned.m8n8.x4.shared.b16 {%0,%1,%2,%3}, [%4];" \
        : "=r"((r)[0]), "=r"((r)[1]), "=r"((r)[2]), "=r"((r)[3]) : "r"(addr))

#define MMA16816(d, a, b) \
    asm volatile("mma.sync.aligned.m16n8k16.row.col.f32.bf16.bf16.f32 " \
        "{%0,%1,%2,%3},{%4,%5,%6,%7},{%8,%9},{%0,%1,%2,%3};" \
        : "+f"((d)[0]), "+f"((d)[1]), "+f"((d)[2]), "+f"((d)[3]) \
        : "r"((a)[0]), "r"((a)[1]), "r"((a)[2]), "r"((a)[3]), \
          "r"((b)[0]), "r"((b)[1]))

// ---------------------------------------------------------------------------
// Kernel P: dense bf16-split weights, chunk-major [t][oc][32].
// ---------------------------------------------------------------------------
__global__ void prep_w_kernel(const float* __restrict__ w_dcn) {
    int i = blockIdx.x * 256 + threadIdx.x;   // < 72*256*32
    int kkl = i & 31;
    int oc  = (i >> 5) & 255;
    int t   = i >> 13;
    int kk  = t * 32 + kkl;
    int c   = kk / 9;
    int k   = kk - c * 9;
    float w = w_dcn[(oc * CIN + c) * KKN + k];
    __nv_bfloat16 h = __float2bfloat16(w);
    g_wbh[i] = h;
    g_wbl[i] = __float2bfloat16(w - __bfloat162float(h));
}

// ---------------------------------------------------------------------------
// Kernel A: offset/mask conv (27 oc, 3x3, pad 1) + bias + sigmoid.
// ---------------------------------------------------------------------------
__global__ __launch_bounds__(256) void om_kernel(
    const float* __restrict__ input,
    const float* __restrict__ w_om,
    const float* __restrict__ b_om) {
    __shared__ float s_in[4][3 * 68];
    __shared__ float s_w[4][244];

    const int y   = blockIdx.x;
    const int b   = blockIdx.y;
    const int tid = threadIdx.x;
    const int oc  = tid >> 3;
    const int x0  = (tid & 7) << 3;

    float acc[8];
#pragma unroll
    for (int i = 0; i < 8; ++i) acc[i] = 0.f;

    for (int c0 = 0; c0 < CIN; c0 += 4) {
        __syncthreads();
        if (tid < 198) {
            int r  = tid / 66;
            int xi = tid - r * 66;
            int xx = xi - 1, yy = y - 1 + r;
            bool ok = (yy >= 0 && yy < HW && xx >= 0 && xx < HW);
            int yyc = min(max(yy, 0), HW - 1), xxc = min(max(xx, 0), HW - 1);
            const float* base = input + (((size_t)b * CIN + c0) * HW + yyc) * HW + xxc;
#pragma unroll
            for (int cc = 0; cc < 4; ++cc)
                s_in[cc][r * 68 + xi] = ok ? base[cc * HW * HW] : 0.f;
        }
        for (int j = tid; j < 972; j += 256) {
            int cc = j / 243, t = j - cc * 243;
            int o = t / 9, k = t - o * 9;
            s_w[cc][t] = w_om[(o * CIN + c0 + cc) * KKN + k];
        }
        __syncthreads();
        if (oc < 27) {
#pragma unroll
            for (int cc = 0; cc < 4; ++cc) {
#pragma unroll
                for (int r = 0; r < 3; ++r) {
                    float w0 = s_w[cc][oc * 9 + r * 3 + 0];
                    float w1 = s_w[cc][oc * 9 + r * 3 + 1];
                    float w2 = s_w[cc][oc * 9 + r * 3 + 2];
                    const float* row = s_in[cc] + r * 68 + x0;
                    float v0 = row[0], v1 = row[1];
#pragma unroll
                    for (int xi = 0; xi < 8; ++xi) {
                        float v2 = row[xi + 2];
                        acc[xi] += w0 * v0 + w1 * v1 + w2 * v2;
                        v0 = v1; v1 = v2;
                    }
                }
            }
        }
    }

    if (oc < 27) {
        const float bias = b_om[oc];
        const int grp = oc / 9;
        const int k   = oc - grp * 9;
        float* dst = g_om + (((size_t)grp * BB + b) * KKN + k) * (HW * HW) + y * HW + x0;
#pragma unroll
        for (int xi = 0; xi < 8; ++xi) {
            float v = acc[xi] + bias;
            if (grp == 2) v = 1.f / (1.f + expf(-v));
            dst[xi] = v;
        }
    }
}

// ---------------------------------------------------------------------------
// Kernel B: fused bilinear sampling + mma.sync GEMM.
// CTA = 512 threads (16 warps), tile M=128 px x N=256 oc, K dense 2304.
// Warp tile 32x64 (4 M-warps x 4 N-warps). Double-buffered smem.
// Rows padded to 80 B -> conflict-free ldmatrix/STS (stride 20 banks).
// Staging lane map px-major: warp = 32 consecutive px at same tap -> coalesced.
// ---------------------------------------------------------------------------
#define ABYTES 10240            // 128 rows * 80 B (one split)
#define BBYTES 20480            // 256 rows * 80 B (one split)
#define STGB   61440            // Ah | Al | Bh | Bl
#define SM_WM  0                // float4[1152]
#define SM_IM  18432            // ushort4[1152]
#define SM_BUF 27648
#define SM_TOTAL (SM_BUF + 2 * STGB)   // 150528

__device__ __forceinline__ void stage_chunk(
    char* smem, int bufoff, int t, int b, int tid,
    const float4* s_wm4, const ushort4* s_im4,
    const float* __restrict__ input) {
    // ---- B: (split = tid>>8, oc = tid&255), 64 B contiguous ----
    {
        const int oc = tid & 255;
        const __nv_bfloat16* srcp = (tid < 256) ? g_wbh : g_wbl;
        const uint4* src = (const uint4*)(srcp + ((size_t)t * COUT + oc) * 32);
        char* dst = smem + bufoff + 2 * ABYTES + ((tid >> 8) ? BBYTES : 0) + oc * 80;
#pragma unroll
        for (int q = 0; q < 4; ++q)
            *(uint4*)(dst + q * 16) = src[q];
    }
    // ---- A: px-major. thread = (px = tid&127, kgroup = tid>>7), 8 samples ----
    const int px = tid & 127;
    const int kg = tid >> 7;              // 0..3
    const int kks = t * 32 + kg * 8;
    int c = kks / 9;
    int k = kks - c * 9;
    const float* pl = input + (((size_t)b * CIN + c) << 12);
    const int mbase = (px >> 6) * 576 + (px & 63);
    uint hi[4], lo[4];
#pragma unroll
    for (int i = 0; i < 8; ++i) {
        int m = mbase + k * 64;
        float4  w4 = s_wm4[m];
        ushort4 i4 = s_im4[m];
        float v = w4.x * __ldg(pl + i4.x) + w4.y * __ldg(pl + i4.y)
                + w4.z * __ldg(pl + i4.z) + w4.w * __ldg(pl + i4.w);
        __nv_bfloat16 h = __float2bfloat16(v);
        __nv_bfloat16 l = __float2bfloat16(v - __bfloat162float(h));
        uint hu = (uint)__bfloat16_as_ushort(h);
        uint lu = (uint)__bfloat16_as_ushort(l);
        if (i & 1) { hi[i >> 1] |= hu << 16; lo[i >> 1] |= lu << 16; }
        else       { hi[i >> 1]  = hu;       lo[i >> 1]  = lu; }
        if (++k == 9) { k = 0; pl += HW * HW; }
    }
    char* Ah = smem + bufoff + px * 80 + kg * 16;
    *(uint4*)(Ah)          = make_uint4(hi[0], hi[1], hi[2], hi[3]);
    *(uint4*)(Ah + ABYTES) = make_uint4(lo[0], lo[1], lo[2], lo[3]);
}

__global__ __launch_bounds__(512, 1) void dcn_main_mma(
    const float* __restrict__ input,
    const float* __restrict__ b_dcn,
    float* __restrict__ out) {
    extern __shared__ char smem[];
    const int tid  = threadIdx.x;
    const int wid  = tid >> 5;
    const int lane = tid & 31;
    const int b    = blockIdx.y;
    const int y0   = blockIdx.x * 2;

    const uint sbase = smem_u32(smem);
    float4*  s_wm4 = (float4*)(smem + SM_WM);
    ushort4* s_im4 = (ushort4*)(smem + SM_IM);

    // Phase 1: bilinear metadata for 2 rows x 9 taps x 64 px (mask folded).
    for (int j = tid; j < 1152; j += 512) {
        int rs  = j / 576;
        int rem = j - rs * 576;
        int k   = rem >> 6;
        int px  = rem & 63;
        int y   = y0 + rs;
        const float* p = g_om + (((size_t)b * KKN + k) * HW + y) * HW + px;
        float dy = p[0];
        float dx = p[(size_t)BB * KKN * HW * HW];
        float m  = p[(size_t)2 * BB * KKN * HW * HW];
        int ki = k / 3, kj = k - ki * 3;
        float py  = (float)(y - 1 + ki) + dy;
        float pxx = (float)(px - 1 + kj) + dx;
        float y0f = floorf(py), x0f = floorf(pxx);
        float ly = py - y0f, lx = pxx - x0f;
        int yy0 = (int)y0f, xx0 = (int)x0f;
        int yy1 = yy0 + 1,  xx1 = xx0 + 1;
        bool vy0 = (yy0 >= 0) && (yy0 < HW);
        bool vy1 = (yy1 >= 0) && (yy1 < HW);
        bool vx0 = (xx0 >= 0) && (xx0 < HW);
        bool vx1 = (xx1 >= 0) && (xx1 < HW);
        int cy0 = min(max(yy0, 0), HW - 1), cy1 = min(max(yy1, 0), HW - 1);
        int cx0 = min(max(xx0, 0), HW - 1), cx1 = min(max(xx1, 0), HW - 1);
        float w00 = (vy0 && vx0) ? (1.f - ly) * (1.f - lx) * m : 0.f;
        float w01 = (vy0 && vx1) ? (1.f - ly) * lx * m : 0.f;
        float w10 = (vy1 && vx0) ? ly * (1.f - lx) * m : 0.f;
        float w11 = (vy1 && vx1) ? ly * lx * m : 0.f;
        s_wm4[j] = make_float4(w00, w01, w10, w11);
        s_im4[j] = make_ushort4((ushort)(cy0 * HW + cx0), (ushort)(cy0 * HW + cx1),
                                (ushort)(cy1 * HW + cx0), (ushort)(cy1 * HW + cx1));
    }
    __syncthreads();

    // Warp tiling: 4 warps along M (32 each), 4 along N (64 each).
    const int mwarp = (wid & 3) * 32;
    const int nwarp = (wid >> 2) * 64;
    const uint aLane = (uint)((mwarp + (lane & 15)) * 80 + ((lane >> 4) & 1) * 16);
    const uint bLane = (uint)((nwarp + (lane & 7) + ((lane >> 4) & 1) * 8) * 80
                              + ((lane >> 3) & 1) * 16);

    float acc[2][8][4];
#pragma unroll
    for (int mt = 0; mt < 2; ++mt)
#pragma unroll
        for (int nt = 0; nt < 8; ++nt)
#pragma unroll
            for (int q = 0; q < 4; ++q) acc[mt][nt][q] = 0.f;

    stage_chunk(smem, SM_BUF, 0, b, tid, s_wm4, s_im4, input);
    __syncthreads();

#pragma unroll 1
    for (int t = 0; t < CHUNKS; ++t) {
        const int s = t & 1;
        if (t + 1 < CHUNKS)
            stage_chunk(smem, SM_BUF + (s ^ 1) * STGB, t + 1, b, tid, s_wm4, s_im4, input);

        const uint aBase = sbase + SM_BUF + s * STGB + aLane;
        const uint bBase = sbase + SM_BUF + s * STGB + 2 * ABYTES + bLane;
#pragma unroll
        for (int ks = 0; ks < 2; ++ks) {
            uint ah[2][4], al[2][4];
#pragma unroll
            for (int mt = 0; mt < 2; ++mt) {
                uint aa = aBase + mt * (16 * 80) + ks * 32;
                LDM_X4(ah[mt], aa);
                LDM_X4(al[mt], aa + ABYTES);
            }
#pragma unroll
            for (int g = 0; g < 4; ++g) {
                uint bh[4], bl[4];
                uint ba = bBase + g * (16 * 80) + ks * 32;
                LDM_X4(bh, ba);
                LDM_X4(bl, ba + BBYTES);
#pragma unroll
                for (int mt = 0; mt < 2; ++mt) {
                    MMA16816(acc[mt][2 * g],     ah[mt], bh);
                    MMA16816(acc[mt][2 * g],     ah[mt], bl);
                    MMA16816(acc[mt][2 * g],     al[mt], bh);
                    MMA16816(acc[mt][2 * g + 1], ah[mt], bh + 2);
                    MMA16816(acc[mt][2 * g + 1], ah[mt], bl + 2);
                    MMA16816(acc[mt][2 * g + 1], al[mt], bh + 2);
                }
            }
        }
        __syncthreads();
    }

    // Epilogue: register accumulators -> gmem, bias added.
    const int tq = lane >> 2, tr = lane & 3;
    float bz[8][2];
#pragma unroll
    for (int nt = 0; nt < 8; ++nt) {
        int oc = nwarp + nt * 8 + tr * 2;
        bz[nt][0] = __ldg(b_dcn + oc);
        bz[nt][1] = __ldg(b_dcn + oc + 1);
    }
    const int ybase = y0 + (mwarp >> 6);
    const int xbase = mwarp & 63;
#pragma unroll
    for (int mt = 0; mt < 2; ++mt) {
        int x = xbase + mt * 16 + tq;
#pragma unroll
        for (int nt = 0; nt < 8; ++nt) {
            int oc = nwarp + nt * 8 + tr * 2;
            float* orow = out + ((size_t)(b * COUT + oc)) * (HW * HW) + ybase * HW + x;
            orow[0]           = acc[mt][nt][0] + bz[nt][0];
            orow[HW * HW]     = acc[mt][nt][1] + bz[nt][1];
            orow[8]           = acc[mt][nt][2] + bz[nt][0];
            orow[HW * HW + 8] = acc[mt][nt][3] + bz[nt][1];
        }
    }
}

// ---------------------------------------------------------------------------
extern "C" void kernel_launch(void* const* d_in, const int* in_sizes, int n_in,
                              void* d_out, int out_size) {
    const float* input = (const float*)d_in[0];
    const float* w_om  = (const float*)d_in[1];
    const float* b_om  = (const float*)d_in[2];
    const float* w_dcn = (const float*)d_in[3];
    const float* b_dcn = (const float*)d_in[4];
    float* out = (float*)d_out;

    cudaFuncSetAttribute(dcn_main_mma,
                         cudaFuncAttributeMaxDynamicSharedMemorySize, SM_TOTAL);

    // om first so the fixed-index ncu capture lands on it.
    om_kernel<<<dim3(HW, BB), 256>>>(input, w_om, b_om);
    prep_w_kernel<<<(CHUNKS * COUT * 32) / 256, 256>>>(w_dcn);
    dcn_main_mma<<<dim3(HW / 2, BB), 512, SM_TOTAL>>>(input, b_dcn, out);
}

// round 10
// speedup vs baseline: 2.0898x; 1.1436x over previous
#include <cuda_runtime.h>
#include <cuda_bf16.h>
#include <cstdint>

// DCNv2 forward. Offset conv on fp32 CUDA cores (2-way channel split, bank-
// conflict-free transposed smem); main einsum on mma.sync bf16 hi/lo split.

typedef unsigned int uint;
typedef unsigned short ushort;

#define BB     8
#define CIN    256
#define COUT   256
#define HW     64
#define KKN    9
#define KTOT   2304
#define CHUNKS 72            // K chunks of 32 (2 k16 steps each)

// ---------------- device scratch (static: allocation-free) ----------------
// om partial sums (no bias/sigmoid), layout per buffer: [grp][b][k][y][x]
__device__ float g_omp0[3 * BB * KKN * HW * HW];
__device__ float g_omp1[3 * BB * KKN * HW * HW];
// dense pre-split weights, chunk-major: [chunk][oc][32] bf16
__device__ __align__(16) __nv_bfloat16 g_wbh[CHUNKS * COUT * 32];
__device__ __align__(16) __nv_bfloat16 g_wbl[CHUNKS * COUT * 32];

__device__ __forceinline__ uint smem_u32(const void* p) {
    uint a;
    asm("{ .reg .u64 t; cvta.to.shared.u64 t, %1; cvt.u32.u64 %0, t; }"
        : "=r"(a) : "l"(p));
    return a;
}

#define LDM_X4(r, addr) \
    asm volatile("ldmatrix.sync.aligned.m8n8.x4.shared.b16 {%0,%1,%2,%3}, [%4];" \
        : "=r"((r)[0]), "=r"((r)[1]), "=r"((r)[2]), "=r"((r)[3]) : "r"(addr))

#define MMA16816(d, a, b) \
    asm volatile("mma.sync.aligned.m16n8k16.row.col.f32.bf16.bf16.f32 " \
        "{%0,%1,%2,%3},{%4,%5,%6,%7},{%8,%9},{%0,%1,%2,%3};" \
        : "+f"((d)[0]), "+f"((d)[1]), "+f"((d)[2]), "+f"((d)[3]) \
        : "r"((a)[0]), "r"((a)[1]), "r"((a)[2]), "r"((a)[3]), \
          "r"((b)[0]), "r"((b)[1]))

// ---------------------------------------------------------------------------
// Kernel P: dense bf16-split weights, chunk-major [t][oc][32].
// ---------------------------------------------------------------------------
__global__ void prep_w_kernel(const float* __restrict__ w_dcn) {
    int i = blockIdx.x * 256 + threadIdx.x;   // < 72*256*32
    int kkl = i & 31;
    int oc  = (i >> 5) & 255;
    int t   = i >> 13;
    int kk  = t * 32 + kkl;
    int c   = kk / 9;
    int k   = kk - c * 9;
    float w = w_dcn[(oc * CIN + c) * KKN + k];
    __nv_bfloat16 h = __float2bfloat16(w);
    g_wbh[i] = h;
    g_wbl[i] = __float2bfloat16(w - __bfloat162float(h));
}

// ---------------------------------------------------------------------------
// Kernel A: offset/mask conv partial (128 channels per z). No bias/sigmoid
// here (folded into main's meta phase). Conflict-free transposed s_in:
// value for x' (=x+1, 0..65) stored at slot (x'&7)*9 + (x'>>3)  (72 words).
// Compute thread (oc, xg) reads tap j at slot j*9+xg / xg+1 / xg+10 — all
// consecutive-in-xg -> bank-conflict-free broadcast.
// ---------------------------------------------------------------------------
__global__ __launch_bounds__(256) void om_kernel(
    const float* __restrict__ input,
    const float* __restrict__ w_om) {
    __shared__ float s_in[4][3][72];
    __shared__ float s_w[4][244];

    const int y   = blockIdx.x;
    const int b   = blockIdx.y;
    const int z   = blockIdx.z;          // channel half
    const int tid = threadIdx.x;
    const int oc  = tid >> 3;
    const int xg  = tid & 7;
    const int x0  = xg << 3;

    float acc[8];
#pragma unroll
    for (int i = 0; i < 8; ++i) acc[i] = 0.f;

    for (int cc0 = 0; cc0 < 128; cc0 += 4) {
        const int c0 = z * 128 + cc0;
        __syncthreads();
        if (tid < 198) {
            int r  = tid / 66;
            int xp = tid - r * 66;            // x' in 0..65  (x = xp-1)
            int xx = xp - 1, yy = y - 1 + r;
            bool ok = (yy >= 0 && yy < HW && xx >= 0 && xx < HW);
            int yyc = min(max(yy, 0), HW - 1), xxc = min(max(xx, 0), HW - 1);
            const float* base = input + (((size_t)b * CIN + c0) * HW + yyc) * HW + xxc;
            int slot = (xp & 7) * 9 + (xp >> 3);
#pragma unroll
            for (int cc = 0; cc < 4; ++cc)
                s_in[cc][r][slot] = ok ? base[cc * HW * HW] : 0.f;
        }
        for (int j = tid; j < 972; j += 256) {
            int cc = j / 243, t = j - cc * 243;
            int o = t / 9, k = t - o * 9;
            s_w[cc][t] = w_om[(o * CIN + c0 + cc) * KKN + k];
        }
        __syncthreads();
        if (oc < 27) {
#pragma unroll
            for (int cc = 0; cc < 4; ++cc) {
#pragma unroll
                for (int r = 0; r < 3; ++r) {
                    const float* row = s_in[cc][r];
                    float v[10];
#pragma unroll
                    for (int j = 0; j < 8; ++j) v[j] = row[j * 9 + xg];
                    v[8] = row[xg + 1];
                    v[9] = row[xg + 10];
                    float w0 = s_w[cc][oc * 9 + r * 3 + 0];
                    float w1 = s_w[cc][oc * 9 + r * 3 + 1];
                    float w2 = s_w[cc][oc * 9 + r * 3 + 2];
#pragma unroll
                    for (int xi = 0; xi < 8; ++xi)
                        acc[xi] += w0 * v[xi] + w1 * v[xi + 1] + w2 * v[xi + 2];
                }
            }
        }
    }

    if (oc < 27) {
        const int grp = oc / 9;
        const int k   = oc - grp * 9;
        float* buf = z ? g_omp1 : g_omp0;
        float* dst = buf + (((size_t)grp * BB + b) * KKN + k) * (HW * HW) + y * HW + x0;
#pragma unroll
        for (int xi = 0; xi < 8; ++xi) dst[xi] = acc[xi];
    }
}

// ---------------------------------------------------------------------------
// Kernel B: fused bilinear sampling + mma.sync GEMM.
// CTA = 512 threads (16 warps), tile M=128 px x N=256 oc, K dense 2304.
// Warp tile 32x64. Double-buffered smem, px-major coalesced gathers.
// ---------------------------------------------------------------------------
#define ABYTES 10240            // 128 rows * 80 B (one split)
#define BBYTES 20480            // 256 rows * 80 B (one split)
#define STGB   61440            // Ah | Al | Bh | Bl
#define SM_WM  0                // float4[1152]
#define SM_IM  18432            // ushort4[1152]
#define SM_BUF 27648
#define SM_TOTAL (SM_BUF + 2 * STGB)   // 150528

__device__ __forceinline__ void stage_chunk(
    char* smem, int bufoff, int t, int b, int tid,
    const float4* s_wm4, const ushort4* s_im4,
    const float* __restrict__ input) {
    // ---- B: (split = tid>>8, oc = tid&255), 64 B contiguous ----
    {
        const int oc = tid & 255;
        const __nv_bfloat16* srcp = (tid < 256) ? g_wbh : g_wbl;
        const uint4* src = (const uint4*)(srcp + ((size_t)t * COUT + oc) * 32);
        char* dst = smem + bufoff + 2 * ABYTES + ((tid >> 8) ? BBYTES : 0) + oc * 80;
#pragma unroll
        for (int q = 0; q < 4; ++q)
            *(uint4*)(dst + q * 16) = src[q];
    }
    // ---- A: px-major, 8 samples per thread, gathered in pairs (MLP=8) ----
    const int px = tid & 127;
    const int kg = tid >> 7;              // 0..3
    const int kks = t * 32 + kg * 8;
    int c = kks / 9;
    int k = kks - c * 9;
    const float* pl = input + (((size_t)b * CIN + c) << 12);
    const int mbase = (px >> 6) * 576 + (px & 63);
    uint hi[4], lo[4];
#pragma unroll
    for (int i = 0; i < 8; i += 2) {
        // sample i
        int mA = mbase + k * 64;
        const float* plA = pl;
        float4  wA = s_wm4[mA];
        ushort4 iA = s_im4[mA];
        if (++k == 9) { k = 0; pl += HW * HW; }
        // sample i+1
        int mB = mbase + k * 64;
        const float* plB = pl;
        float4  wB = s_wm4[mB];
        ushort4 iB = s_im4[mB];
        if (++k == 9) { k = 0; pl += HW * HW; }
        // 8 loads in flight
        float a0 = __ldg(plA + iA.x), a1 = __ldg(plA + iA.y);
        float a2 = __ldg(plA + iA.z), a3 = __ldg(plA + iA.w);
        float b0 = __ldg(plB + iB.x), b1 = __ldg(plB + iB.y);
        float b2 = __ldg(plB + iB.z), b3 = __ldg(plB + iB.w);
        float vA = wA.x * a0 + wA.y * a1 + wA.z * a2 + wA.w * a3;
        float vB = wB.x * b0 + wB.y * b1 + wB.z * b2 + wB.w * b3;
        __nv_bfloat16 hA = __float2bfloat16(vA);
        __nv_bfloat16 lA = __float2bfloat16(vA - __bfloat162float(hA));
        __nv_bfloat16 hB = __float2bfloat16(vB);
        __nv_bfloat16 lB = __float2bfloat16(vB - __bfloat162float(hB));
        hi[i >> 1] = (uint)__bfloat16_as_ushort(hA) | ((uint)__bfloat16_as_ushort(hB) << 16);
        lo[i >> 1] = (uint)__bfloat16_as_ushort(lA) | ((uint)__bfloat16_as_ushort(lB) << 16);
    }
    char* Ah = smem + bufoff + px * 80 + kg * 16;
    *(uint4*)(Ah)          = make_uint4(hi[0], hi[1], hi[2], hi[3]);
    *(uint4*)(Ah + ABYTES) = make_uint4(lo[0], lo[1], lo[2], lo[3]);
}

__global__ __launch_bounds__(512, 1) void dcn_main_mma(
    const float* __restrict__ input,
    const float* __restrict__ b_om,
    const float* __restrict__ b_dcn,
    float* __restrict__ out) {
    extern __shared__ char smem[];
    const int tid  = threadIdx.x;
    const int wid  = tid >> 5;
    const int lane = tid & 31;
    const int b    = blockIdx.y;
    const int y0   = blockIdx.x * 2;

    const uint sbase = smem_u32(smem);
    float4*  s_wm4 = (float4*)(smem + SM_WM);
    ushort4* s_im4 = (ushort4*)(smem + SM_IM);

    const size_t GSTR = (size_t)BB * KKN * HW * HW;   // group stride

    // Phase 1: bilinear metadata; sums the two om partials + bias + sigmoid.
    for (int j = tid; j < 1152; j += 512) {
        int rs  = j / 576;
        int rem = j - rs * 576;
        int k   = rem >> 6;
        int px  = rem & 63;
        int y   = y0 + rs;
        size_t off = (((size_t)b * KKN + k) * HW + y) * HW + px;
        const float* p0 = g_omp0 + off;
        const float* p1 = g_omp1 + off;
        float dy = p0[0]        + p1[0]        + __ldg(b_om + k);
        float dx = p0[GSTR]     + p1[GSTR]     + __ldg(b_om + 9 + k);
        float mv = p0[2 * GSTR] + p1[2 * GSTR] + __ldg(b_om + 18 + k);
        float m  = 1.f / (1.f + expf(-mv));
        int ki = k / 3, kj = k - ki * 3;
        float py  = (float)(y - 1 + ki) + dy;
        float pxx = (float)(px - 1 + kj) + dx;
        float y0f = floorf(py), x0f = floorf(pxx);
        float ly = py - y0f, lx = pxx - x0f;
        int yy0 = (int)y0f, xx0 = (int)x0f;
        int yy1 = yy0 + 1,  xx1 = xx0 + 1;
        bool vy0 = (yy0 >= 0) && (yy0 < HW);
        bool vy1 = (yy1 >= 0) && (yy1 < HW);
        bool vx0 = (xx0 >= 0) && (xx0 < HW);
        bool vx1 = (xx1 >= 0) && (xx1 < HW);
        int cy0 = min(max(yy0, 0), HW - 1), cy1 = min(max(yy1, 0), HW - 1);
        int cx0 = min(max(xx0, 0), HW - 1), cx1 = min(max(xx1, 0), HW - 1);
        float w00 = (vy0 && vx0) ? (1.f - ly) * (1.f - lx) * m : 0.f;
        float w01 = (vy0 && vx1) ? (1.f - ly) * lx * m : 0.f;
        float w10 = (vy1 && vx0) ? ly * (1.f - lx) * m : 0.f;
        float w11 = (vy1 && vx1) ? ly * lx * m : 0.f;
        s_wm4[j] = make_float4(w00, w01, w10, w11);
        s_im4[j] = make_ushort4((ushort)(cy0 * HW + cx0), (ushort)(cy0 * HW + cx1),
                                (ushort)(cy1 * HW + cx0), (ushort)(cy1 * HW + cx1));
    }
    __syncthreads();

    // Warp tiling: 4 warps along M (32 each), 4 along N (64 each).
    const int mwarp = (wid & 3) * 32;
    const int nwarp = (wid >> 2) * 64;
    const uint aLane = (uint)((mwarp + (lane & 15)) * 80 + ((lane >> 4) & 1) * 16);
    const uint bLane = (uint)((nwarp + (lane & 7) + ((lane >> 4) & 1) * 8) * 80
                              + ((lane >> 3) & 1) * 16);

    float acc[2][8][4];
#pragma unroll
    for (int mt = 0; mt < 2; ++mt)
#pragma unroll
        for (int nt = 0; nt < 8; ++nt)
#pragma unroll
            for (int q = 0; q < 4; ++q) acc[mt][nt][q] = 0.f;

    stage_chunk(smem, SM_BUF, 0, b, tid, s_wm4, s_im4, input);
    __syncthreads();

#pragma unroll 1
    for (int t = 0; t < CHUNKS; ++t) {
        const int s = t & 1;
        if (t + 1 < CHUNKS)
            stage_chunk(smem, SM_BUF + (s ^ 1) * STGB, t + 1, b, tid, s_wm4, s_im4, input);

        const uint aBase = sbase + SM_BUF + s * STGB + aLane;
        const uint bBase = sbase + SM_BUF + s * STGB + 2 * ABYTES + bLane;
#pragma unroll
        for (int ks = 0; ks < 2; ++ks) {
            uint ah[2][4], al[2][4];
#pragma unroll
            for (int mt = 0; mt < 2; ++mt) {
                uint aa = aBase + mt * (16 * 80) + ks * 32;
                LDM_X4(ah[mt], aa);
                LDM_X4(al[mt], aa + ABYTES);
            }
#pragma unroll
            for (int g = 0; g < 4; ++g) {
                uint bh[4], bl[4];
                uint ba = bBase + g * (16 * 80) + ks * 32;
                LDM_X4(bh, ba);
                LDM_X4(bl, ba + BBYTES);
#pragma unroll
                for (int mt = 0; mt < 2; ++mt) {
                    MMA16816(acc[mt][2 * g],     ah[mt], bh);
                    MMA16816(acc[mt][2 * g],     ah[mt], bl);
                    MMA16816(acc[mt][2 * g],     al[mt], bh);
                    MMA16816(acc[mt][2 * g + 1], ah[mt], bh + 2);
                    MMA16816(acc[mt][2 * g + 1], ah[mt], bl + 2);
                    MMA16816(acc[mt][2 * g + 1], al[mt], bh + 2);
                }
            }
        }
        __syncthreads();
    }

    // Epilogue
    const int tq = lane >> 2, tr = lane & 3;
    float bz[8][2];
#pragma unroll
    for (int nt = 0; nt < 8; ++nt) {
        int oc = nwarp + nt * 8 + tr * 2;
        bz[nt][0] = __ldg(b_dcn + oc);
        bz[nt][1] = __ldg(b_dcn + oc + 1);
    }
    const int ybase = y0 + (mwarp >> 6);
    const int xbase = mwarp & 63;
#pragma unroll
    for (int mt = 0; mt < 2; ++mt) {
        int x = xbase + mt * 16 + tq;
#pragma unroll
        for (int nt = 0; nt < 8; ++nt) {
            int oc = nwarp + nt * 8 + tr * 2;
            float* orow = out + ((size_t)(b * COUT + oc)) * (HW * HW) + ybase * HW + x;
            orow[0]           = acc[mt][nt][0] + bz[nt][0];
            orow[HW * HW]     = acc[mt][nt][1] + bz[nt][1];
            orow[8]           = acc[mt][nt][2] + bz[nt][0];
            orow[HW * HW + 8] = acc[mt][nt][3] + bz[nt][1];
        }
    }
}

// ---------------------------------------------------------------------------
extern "C" void kernel_launch(void* const* d_in, const int* in_sizes, int n_in,
                              void* d_out, int out_size) {
    const float* input = (const float*)d_in[0];
    const float* w_om  = (const float*)d_in[1];
    const float* b_om  = (const float*)d_in[2];
    const float* w_dcn = (const float*)d_in[3];
    const float* b_dcn = (const float*)d_in[4];
    float* out = (float*)d_out;

    cudaFuncSetAttribute(dcn_main_mma,
                         cudaFuncAttributeMaxDynamicSharedMemorySize, SM_TOTAL);

    // om first so the fixed-index ncu capture lands on it (verifies om fix).
    om_kernel<<<dim3(HW, BB, 2), 256>>>(input, w_om);
    prep_w_kernel<<<(CHUNKS * COUT * 32) / 256, 256>>>(w_dcn);
    dcn_main_mma<<<dim3(HW / 2, BB), 512, SM_TOTAL>>>(input, b_om, b_dcn, out);
}

// round 12
// speedup vs baseline: 2.2335x; 1.0688x over previous
#include <cuda_runtime.h>
#include <cuda_bf16.h>
#include <cstdint>

// DCNv2 forward. BOTH convs on tensor cores (mma.sync m16n8k16 bf16 hi/lo
// split, Ootomo 3-term). om conv = regular-im2col GEMM (M=256px, N=32(27),
// K=2304); main = deformable-gather GEMM (M=128px, N=256, K=2304).
// R11 fix: prep_wo MUST precede om2 (R11 ran om2 on uninitialized weights).

typedef unsigned int uint;
typedef unsigned short ushort;

#define BB     8
#define CIN    256
#define COUT   256
#define HW     64
#define KKN    9
#define KTOT   2304
#define CHUNKS 72            // K chunks of 32 (2 k16 steps each)

// ---------------- device scratch (static: allocation-free) ----------------
// g_om layout: [grp(0=dy,1=dx,2=sig(mask))][b][k][y][x]  (bias+sigmoid done)
__device__ float g_om[3 * BB * KKN * HW * HW];
// dense pre-split main weights, chunk-major: [chunk][oc 256][32] bf16
__device__ __align__(16) __nv_bfloat16 g_wbh[CHUNKS * COUT * 32];
__device__ __align__(16) __nv_bfloat16 g_wbl[CHUNKS * COUT * 32];
// pre-split om weights, chunk-major padded: [chunk][oc 32][32] bf16
__device__ __align__(16) __nv_bfloat16 g_wobh[CHUNKS * 32 * 32];
__device__ __align__(16) __nv_bfloat16 g_wobl[CHUNKS * 32 * 32];

__device__ __forceinline__ uint smem_u32(const void* p) {
    uint a;
    asm("{ .reg .u64 t; cvta.to.shared.u64 t, %1; cvt.u32.u64 %0, t; }"
        : "=r"(a) : "l"(p));
    return a;
}

#define LDM_X4(r, addr) \
    asm volatile("ldmatrix.sync.aligned.m8n8.x4.shared.b16 {%0,%1,%2,%3}, [%4];" \
        : "=r"((r)[0]), "=r"((r)[1]), "=r"((r)[2]), "=r"((r)[3]) : "r"(addr))

#define MMA16816(d, a, b) \
    asm volatile("mma.sync.aligned.m16n8k16.row.col.f32.bf16.bf16.f32 " \
        "{%0,%1,%2,%3},{%4,%5,%6,%7},{%8,%9},{%0,%1,%2,%3};" \
        : "+f"((d)[0]), "+f"((d)[1]), "+f"((d)[2]), "+f"((d)[3]) \
        : "r"((a)[0]), "r"((a)[1]), "r"((a)[2]), "r"((a)[3]), \
          "r"((b)[0]), "r"((b)[1]))

// ---------------------------------------------------------------------------
// Kernel P1: dense bf16-split main weights, chunk-major [t][oc][32].
// ---------------------------------------------------------------------------
__global__ void prep_w_kernel(const float* __restrict__ w_dcn) {
    int i = blockIdx.x * 256 + threadIdx.x;   // < 72*256*32
    int kkl = i & 31;
    int oc  = (i >> 5) & 255;
    int t   = i >> 13;
    int kk  = t * 32 + kkl;
    int c   = kk / 9;
    int k   = kk - c * 9;
    float w = w_dcn[(oc * CIN + c) * KKN + k];
    __nv_bfloat16 h = __float2bfloat16(w);
    g_wbh[i] = h;
    g_wbl[i] = __float2bfloat16(w - __bfloat162float(h));
}

// ---------------------------------------------------------------------------
// Kernel P2: om weights, padded to 32 oc, chunk-major [t][oc32][32].
// ---------------------------------------------------------------------------
__global__ void prep_wo_kernel(const float* __restrict__ w_om) {
    int i = blockIdx.x * 256 + threadIdx.x;   // < 72*32*32 = 73728
    int kkl = i & 31;
    int oc  = (i >> 5) & 31;
    int t   = i >> 10;
    int kk  = t * 32 + kkl;
    int c   = kk / 9;
    int k   = kk - c * 9;
    float w = (oc < 27) ? w_om[(oc * CIN + c) * KKN + k] : 0.f;
    __nv_bfloat16 h = __float2bfloat16(w);
    g_wobh[i] = h;
    g_wobl[i] = __float2bfloat16(w - __bfloat162float(h));
}

// ---------------------------------------------------------------------------
// Kernel A (om2): offset/mask conv as mma GEMM. CTA = 4 image rows (256 px)
// x 32 oc (27 real). 512 threads, 16 warps, warp tile M16 x N32.
// A staged by regular im2col (coalesced LDG), double-buffered.
// ---------------------------------------------------------------------------
#define A2BYTES 20480           // 256 rows * 80 B (one split)
#define B2BYTES 2560            // 32 rows * 80 B (one split)
#define STGB2   46080           // Ah | Al | Bh | Bl
#define SM2_TOTAL (2 * STGB2)   // 92160

__device__ __forceinline__ void stage_om(
    char* smem, int bufoff, int t, int b, int y0, int tid,
    const float* __restrict__ input) {
    // ---- B: threads 0..63 ----
    if (tid < 64) {
        int oc = tid & 31;
        const __nv_bfloat16* srcp = (tid < 32) ? g_wobh : g_wobl;
        const uint4* src = (const uint4*)(srcp + ((size_t)t * 32 + oc) * 32);
        char* dst = smem + bufoff + 2 * A2BYTES + ((tid >= 32) ? B2BYTES : 0) + oc * 80;
#pragma unroll
        for (int q = 0; q < 4; ++q)
            *(uint4*)(dst + q * 16) = src[q];
    }
    // ---- A: thread = (px = tid&255, kg = tid>>8 in 0..1), 16 samples ----
    const int px = tid & 255;
    const int kg = tid >> 8;
    const int x  = px & 63;
    const int y  = y0 + (px >> 6);
    const int kks = t * 32 + kg * 16;
    int c = kks / 9;
    int k = kks - c * 9;
    const float* pl = input + (((size_t)b * CIN + c) << 12);
    uint hi[8], lo[8];
#pragma unroll
    for (int i = 0; i < 16; ++i) {
        int ki = k / 3, kj = k - ki * 3;
        int yy = y - 1 + ki, xx = x - 1 + kj;
        float v = 0.f;
        if (yy >= 0 && yy < HW && xx >= 0 && xx < HW)
            v = __ldg(pl + yy * HW + xx);
        __nv_bfloat16 h = __float2bfloat16(v);
        __nv_bfloat16 l = __float2bfloat16(v - __bfloat162float(h));
        uint hu = (uint)__bfloat16_as_ushort(h);
        uint lu = (uint)__bfloat16_as_ushort(l);
        if (i & 1) { hi[i >> 1] |= hu << 16; lo[i >> 1] |= lu << 16; }
        else       { hi[i >> 1]  = hu;       lo[i >> 1]  = lu; }
        if (++k == 9) { k = 0; pl += HW * HW; }
    }
    char* Ah = smem + bufoff + px * 80 + kg * 32;
#pragma unroll
    for (int q = 0; q < 2; ++q) {
        *(uint4*)(Ah + q * 16)           = make_uint4(hi[q*4], hi[q*4+1], hi[q*4+2], hi[q*4+3]);
        *(uint4*)(Ah + A2BYTES + q * 16) = make_uint4(lo[q*4], lo[q*4+1], lo[q*4+2], lo[q*4+3]);
    }
}

__global__ __launch_bounds__(512, 1) void om2_kernel(
    const float* __restrict__ input,
    const float* __restrict__ b_om) {
    extern __shared__ char smem[];
    const int tid  = threadIdx.x;
    const int wid  = tid >> 5;
    const int lane = tid & 31;
    const int y0   = blockIdx.x * 4;
    const int b    = blockIdx.y;
    const uint sbase = smem_u32(smem);

    const int mwarp = wid * 16;
    const uint aLane = (uint)((mwarp + (lane & 15)) * 80 + ((lane >> 4) & 1) * 16);
    const uint bLane = (uint)(((lane & 7) + ((lane >> 4) & 1) * 8) * 80
                              + ((lane >> 3) & 1) * 16);

    float acc[4][4];
#pragma unroll
    for (int nt = 0; nt < 4; ++nt)
#pragma unroll
        for (int q = 0; q < 4; ++q) acc[nt][q] = 0.f;

    stage_om(smem, 0, 0, b, y0, tid, input);
    __syncthreads();

#pragma unroll 1
    for (int t = 0; t < CHUNKS; ++t) {
        const int s = t & 1;
        if (t + 1 < CHUNKS)
            stage_om(smem, (s ^ 1) * STGB2, t + 1, b, y0, tid, input);

        const uint aBase = sbase + s * STGB2 + aLane;
        const uint bBase = sbase + s * STGB2 + 2 * A2BYTES + bLane;
#pragma unroll
        for (int ks = 0; ks < 2; ++ks) {
            uint ah[4], al[4];
            LDM_X4(ah, aBase + ks * 32);
            LDM_X4(al, aBase + ks * 32 + A2BYTES);
#pragma unroll
            for (int g = 0; g < 2; ++g) {
                uint bh[4], bl[4];
                uint ba = bBase + g * (16 * 80) + ks * 32;
                LDM_X4(bh, ba);
                LDM_X4(bl, ba + B2BYTES);
                MMA16816(acc[2 * g],     ah, bh);
                MMA16816(acc[2 * g],     ah, bl);
                MMA16816(acc[2 * g],     al, bh);
                MMA16816(acc[2 * g + 1], ah, bh + 2);
                MMA16816(acc[2 * g + 1], ah, bl + 2);
                MMA16816(acc[2 * g + 1], al, bh + 2);
            }
        }
        __syncthreads();
    }

    // Epilogue: bias + sigmoid(mask) -> g_om[grp][b][k][y][x]
    const int tq = lane >> 2, tr = lane & 3;
#pragma unroll
    for (int nt = 0; nt < 4; ++nt) {
#pragma unroll
        for (int q = 0; q < 4; ++q) {
            int oc = nt * 8 + tr * 2 + (q & 1);
            if (oc >= 27) continue;
            int px = mwarp + tq + ((q >> 1) ? 8 : 0);
            int y  = y0 + (px >> 6);
            int x  = px & 63;
            float v = acc[nt][q] + __ldg(b_om + oc);
            int grp = oc / 9;
            int k   = oc - grp * 9;
            if (grp == 2) v = 1.f / (1.f + expf(-v));
            g_om[(((size_t)grp * BB + b) * KKN + k) * (HW * HW) + y * HW + x] = v;
        }
    }
}

// ---------------------------------------------------------------------------
// Kernel B: fused bilinear sampling + mma.sync GEMM (verified R9/R10 form).
// ---------------------------------------------------------------------------
#define ABYTES 10240
#define BBYTES 20480
#define STGB   61440
#define SM_WM  0
#define SM_IM  18432
#define SM_BUF 27648
#define SM_TOTAL (SM_BUF + 2 * STGB)   // 150528

__device__ __forceinline__ void stage_chunk(
    char* smem, int bufoff, int t, int b, int tid,
    const float4* s_wm4, const ushort4* s_im4,
    const float* __restrict__ input) {
    {
        const int oc = tid & 255;
        const __nv_bfloat16* srcp = (tid < 256) ? g_wbh : g_wbl;
        const uint4* src = (const uint4*)(srcp + ((size_t)t * COUT + oc) * 32);
        char* dst = smem + bufoff + 2 * ABYTES + ((tid >> 8) ? BBYTES : 0) + oc * 80;
#pragma unroll
        for (int q = 0; q < 4; ++q)
            *(uint4*)(dst + q * 16) = src[q];
    }
    const int px = tid & 127;
    const int kg = tid >> 7;
    const int kks = t * 32 + kg * 8;
    int c = kks / 9;
    int k = kks - c * 9;
    const float* pl = input + (((size_t)b * CIN + c) << 12);
    const int mbase = (px >> 6) * 576 + (px & 63);
    uint hi[4], lo[4];
#pragma unroll
    for (int i = 0; i < 8; i += 2) {
        int mA = mbase + k * 64;
        const float* plA = pl;
        float4  wA = s_wm4[mA];
        ushort4 iA = s_im4[mA];
        if (++k == 9) { k = 0; pl += HW * HW; }
        int mB = mbase + k * 64;
        const float* plB = pl;
        float4  wB = s_wm4[mB];
        ushort4 iB = s_im4[mB];
        if (++k == 9) { k = 0; pl += HW * HW; }
        float a0 = __ldg(plA + iA.x), a1 = __ldg(plA + iA.y);
        float a2 = __ldg(plA + iA.z), a3 = __ldg(plA + iA.w);
        float b0 = __ldg(plB + iB.x), b1 = __ldg(plB + iB.y);
        float b2 = __ldg(plB + iB.z), b3 = __ldg(plB + iB.w);
        float vA = wA.x * a0 + wA.y * a1 + wA.z * a2 + wA.w * a3;
        float vB = wB.x * b0 + wB.y * b1 + wB.z * b2 + wB.w * b3;
        __nv_bfloat16 hA = __float2bfloat16(vA);
        __nv_bfloat16 lA = __float2bfloat16(vA - __bfloat162float(hA));
        __nv_bfloat16 hB = __float2bfloat16(vB);
        __nv_bfloat16 lB = __float2bfloat16(vB - __bfloat162float(hB));
        hi[i >> 1] = (uint)__bfloat16_as_ushort(hA) | ((uint)__bfloat16_as_ushort(hB) << 16);
        lo[i >> 1] = (uint)__bfloat16_as_ushort(lA) | ((uint)__bfloat16_as_ushort(lB) << 16);
    }
    char* Ah = smem + bufoff + px * 80 + kg * 16;
    *(uint4*)(Ah)          = make_uint4(hi[0], hi[1], hi[2], hi[3]);
    *(uint4*)(Ah + ABYTES) = make_uint4(lo[0], lo[1], lo[2], lo[3]);
}

__global__ __launch_bounds__(512, 1) void dcn_main_mma(
    const float* __restrict__ input,
    const float* __restrict__ b_dcn,
    float* __restrict__ out) {
    extern __shared__ char smem[];
    const int tid  = threadIdx.x;
    const int wid  = tid >> 5;
    const int lane = tid & 31;
    const int b    = blockIdx.y;
    const int y0   = blockIdx.x * 2;

    const uint sbase = smem_u32(smem);
    float4*  s_wm4 = (float4*)(smem + SM_WM);
    ushort4* s_im4 = (ushort4*)(smem + SM_IM);
    const size_t GSTR = (size_t)BB * KKN * HW * HW;

    for (int j = tid; j < 1152; j += 512) {
        int rs  = j / 576;
        int rem = j - rs * 576;
        int k   = rem >> 6;
        int px  = rem & 63;
        int y   = y0 + rs;
        const float* p = g_om + (((size_t)b * KKN + k) * HW + y) * HW + px;
        float dy = p[0];
        float dx = p[GSTR];
        float m  = p[2 * GSTR];
        int ki = k / 3, kj = k - ki * 3;
        float py  = (float)(y - 1 + ki) + dy;
        float pxx = (float)(px - 1 + kj) + dx;
        float y0f = floorf(py), x0f = floorf(pxx);
        float ly = py - y0f, lx = pxx - x0f;
        int yy0 = (int)y0f, xx0 = (int)x0f;
        int yy1 = yy0 + 1,  xx1 = xx0 + 1;
        bool vy0 = (yy0 >= 0) && (yy0 < HW);
        bool vy1 = (yy1 >= 0) && (yy1 < HW);
        bool vx0 = (xx0 >= 0) && (xx0 < HW);
        bool vx1 = (xx1 >= 0) && (xx1 < HW);
        int cy0 = min(max(yy0, 0), HW - 1), cy1 = min(max(yy1, 0), HW - 1);
        int cx0 = min(max(xx0, 0), HW - 1), cx1 = min(max(xx1, 0), HW - 1);
        float w00 = (vy0 && vx0) ? (1.f - ly) * (1.f - lx) * m : 0.f;
        float w01 = (vy0 && vx1) ? (1.f - ly) * lx * m : 0.f;
        float w10 = (vy1 && vx0) ? ly * (1.f - lx) * m : 0.f;
        float w11 = (vy1 && vx1) ? ly * lx * m : 0.f;
        s_wm4[j] = make_float4(w00, w01, w10, w11);
        s_im4[j] = make_ushort4((ushort)(cy0 * HW + cx0), (ushort)(cy0 * HW + cx1),
                                (ushort)(cy1 * HW + cx0), (ushort)(cy1 * HW + cx1));
    }
    __syncthreads();

    const int mwarp = (wid & 3) * 32;
    const int nwarp = (wid >> 2) * 64;
    const uint aLane = (uint)((mwarp + (lane & 15)) * 80 + ((lane >> 4) & 1) * 16);
    const uint bLane = (uint)((nwarp + (lane & 7) + ((lane >> 4) & 1) * 8) * 80
                              + ((lane >> 3) & 1) * 16);

    float acc[2][8][4];
#pragma unroll
    for (int mt = 0; mt < 2; ++mt)
#pragma unroll
        for (int nt = 0; nt < 8; ++nt)
#pragma unroll
            for (int q = 0; q < 4; ++q) acc[mt][nt][q] = 0.f;

    stage_chunk(smem, SM_BUF, 0, b, tid, s_wm4, s_im4, input);
    __syncthreads();

#pragma unroll 1
    for (int t = 0; t < CHUNKS; ++t) {
        const int s = t & 1;
        if (t + 1 < CHUNKS)
            stage_chunk(smem, SM_BUF + (s ^ 1) * STGB, t + 1, b, tid, s_wm4, s_im4, input);

        const uint aBase = sbase + SM_BUF + s * STGB + aLane;
        const uint bBase = sbase + SM_BUF + s * STGB + 2 * ABYTES + bLane;
#pragma unroll
        for (int ks = 0; ks < 2; ++ks) {
            uint ah[2][4], al[2][4];
#pragma unroll
            for (int mt = 0; mt < 2; ++mt) {
                uint aa = aBase + mt * (16 * 80) + ks * 32;
                LDM_X4(ah[mt], aa);
                LDM_X4(al[mt], aa + ABYTES);
            }
#pragma unroll
            for (int g = 0; g < 4; ++g) {
                uint bh[4], bl[4];
                uint ba = bBase + g * (16 * 80) + ks * 32;
                LDM_X4(bh, ba);
                LDM_X4(bl, ba + BBYTES);
#pragma unroll
                for (int mt = 0; mt < 2; ++mt) {
                    MMA16816(acc[mt][2 * g],     ah[mt], bh);
                    MMA16816(acc[mt][2 * g],     ah[mt], bl);
                    MMA16816(acc[mt][2 * g],     al[mt], bh);
                    MMA16816(acc[mt][2 * g + 1], ah[mt], bh + 2);
                    MMA16816(acc[mt][2 * g + 1], ah[mt], bl + 2);
                    MMA16816(acc[mt][2 * g + 1], al[mt], bh + 2);
                }
            }
        }
        __syncthreads();
    }

    const int tq = lane >> 2, tr = lane & 3;
    float bz[8][2];
#pragma unroll
    for (int nt = 0; nt < 8; ++nt) {
        int oc = nwarp + nt * 8 + tr * 2;
        bz[nt][0] = __ldg(b_dcn + oc);
        bz[nt][1] = __ldg(b_dcn + oc + 1);
    }
    const int ybase = y0 + (mwarp >> 6);
    const int xbase = mwarp & 63;
#pragma unroll
    for (int mt = 0; mt < 2; ++mt) {
        int x = xbase + mt * 16 + tq;
#pragma unroll
        for (int nt = 0; nt < 8; ++nt) {
            int oc = nwarp + nt * 8 + tr * 2;
            float* orow = out + ((size_t)(b * COUT + oc)) * (HW * HW) + ybase * HW + x;
            orow[0]           = acc[mt][nt][0] + bz[nt][0];
            orow[HW * HW]     = acc[mt][nt][1] + bz[nt][1];
            orow[8]           = acc[mt][nt][2] + bz[nt][0];
            orow[HW * HW + 8] = acc[mt][nt][3] + bz[nt][1];
        }
    }
}

// ---------------------------------------------------------------------------
extern "C" void kernel_launch(void* const* d_in, const int* in_sizes, int n_in,
                              void* d_out, int out_size) {
    const float* input = (const float*)d_in[0];
    const float* w_om  = (const float*)d_in[1];
    const float* b_om  = (const float*)d_in[2];
    const float* w_dcn = (const float*)d_in[3];
    const float* b_dcn = (const float*)d_in[4];
    float* out = (float*)d_out;

    cudaFuncSetAttribute(om2_kernel,
                         cudaFuncAttributeMaxDynamicSharedMemorySize, SM2_TOTAL);
    cudaFuncSetAttribute(dcn_main_mma,
                         cudaFuncAttributeMaxDynamicSharedMemorySize, SM_TOTAL);

    // DEPENDENCY ORDER: prep_wo fills om weights BEFORE om2 reads them.
    // (Position 2 in the 4-launch sequence = om2 -> ncu -s 5 lands on it.)
    prep_wo_kernel<<<(CHUNKS * 32 * 32) / 256, 256>>>(w_om);
    om2_kernel<<<dim3(HW / 4, BB), 512, SM2_TOTAL>>>(input, b_om);
    prep_w_kernel<<<(CHUNKS * COUT * 32) / 256, 256>>>(w_dcn);
    dcn_main_mma<<<dim3(HW / 2, BB), 512, SM_TOTAL>>>(input, b_dcn, out);
}